// round 1
// baseline (speedup 1.0000x reference)
#include <cuda_runtime.h>

#define N_NODES 10000
#define E_EDGES 320000
#define HID 256
#define K_HOPS 10
#define D_RNA 2000
#define D_ATAC 5000

// ---------------- scratch (static device allocations; no cudaMalloc) -------
__device__ float g_h[N_NODES * HID];
__device__ float g_xk[N_NODES * HID];
__device__ float g_zcat[N_NODES * 2 * HID];
__device__ float g_t[N_NODES * HID];
__device__ float g_fw[4 * (K_HOPS + 1)];
__device__ int   g_rowptr[2 * (N_NODES + 1)];
__device__ int   g_cols[2 * E_EDGES];
__device__ float g_vals[2 * E_EDGES];
__device__ int   g_cnt[2 * N_NODES];
__device__ int   g_cur[2 * N_NODES];

// ---------------- f32x2 packed math helpers (sm_100+) ----------------------
__device__ __forceinline__ unsigned long long pack2(float lo, float hi) {
    unsigned long long r;
    asm("mov.b64 %0, {%1, %2};" : "=l"(r) : "f"(lo), "f"(hi));
    return r;
}
__device__ __forceinline__ float2 unpack2(unsigned long long v) {
    float2 f;
    asm("mov.b64 {%0, %1}, %2;" : "=f"(f.x), "=f"(f.y) : "l"(v));
    return f;
}
__device__ __forceinline__ void ffma2(unsigned long long& d, unsigned long long a,
                                      unsigned long long b) {
    asm("fma.rn.f32x2 %0, %1, %2, %0;" : "+l"(d) : "l"(a), "l"(b));
}

// ---------------- GEMM: C[M,N] = A[M,K] @ B[K,N] + bias (opt relu) ---------
// 128x128 tile, BK=8, 256 threads, 8x8 per-thread microtile, f32x2 FMAs.
// Requires K % 8 == 0, N % 4 == 0 (true for all call sites here).
__global__ __launch_bounds__(256) void sgemm_bias(
    const float* __restrict__ A, const float* __restrict__ B,
    const float* __restrict__ bias, float* __restrict__ C,
    int M, int N, int K, int relu)
{
    __shared__ float As[8][128];
    __shared__ float Bs[8][128];

    const int tid  = threadIdx.x;
    const int row0 = blockIdx.y * 128;
    const int col0 = blockIdx.x * 128;

    const int a_row = tid >> 1;
    const int a_k   = (tid & 1) * 4;
    const int b_k   = tid >> 5;
    const int b_col = (tid & 31) * 4;
    const int tx    = (tid & 15) * 8;
    const int ty    = (tid >> 4) * 8;

    unsigned long long acc[8][4];
#pragma unroll
    for (int i = 0; i < 8; i++)
#pragma unroll
        for (int j = 0; j < 4; j++) acc[i][j] = 0ull;

    const bool a_ok = (row0 + a_row) < M;
    const bool b_ok = (col0 + b_col) < N;
    const float* Aptr = A + (long long)(row0 + a_row) * K + a_k;
    const float* Bptr = B + (long long)b_k * N + col0 + b_col;

    float4 av = make_float4(0.f, 0.f, 0.f, 0.f);
    float4 bv = make_float4(0.f, 0.f, 0.f, 0.f);
    if (a_ok) av = *(const float4*)Aptr;
    if (b_ok) bv = *(const float4*)Bptr;

    for (int kk = 0; kk < K; kk += 8) {
        As[a_k + 0][a_row] = av.x;
        As[a_k + 1][a_row] = av.y;
        As[a_k + 2][a_row] = av.z;
        As[a_k + 3][a_row] = av.w;
        *(float4*)&Bs[b_k][b_col] = bv;
        __syncthreads();

        // prefetch next K-slab (overlaps with compute)
        float4 av_n = make_float4(0.f, 0.f, 0.f, 0.f);
        float4 bv_n = make_float4(0.f, 0.f, 0.f, 0.f);
        const int kn = kk + 8;
        if (kn < K) {
            if (a_ok) av_n = *(const float4*)(Aptr + kn);
            if (b_ok) bv_n = *(const float4*)(Bptr + (long long)kn * N);
        }

#pragma unroll
        for (int k = 0; k < 8; k++) {
            float4 a0 = *(const float4*)&As[k][ty];
            float4 a1 = *(const float4*)&As[k][ty + 4];
            ulonglong2 bq0 = *(const ulonglong2*)&Bs[k][tx];
            ulonglong2 bq1 = *(const ulonglong2*)&Bs[k][tx + 4];
            unsigned long long bp[4] = {bq0.x, bq0.y, bq1.x, bq1.y};
            float aa[8] = {a0.x, a0.y, a0.z, a0.w, a1.x, a1.y, a1.z, a1.w};
#pragma unroll
            for (int i = 0; i < 8; i++) {
                unsigned long long asp = pack2(aa[i], aa[i]);
#pragma unroll
                for (int j = 0; j < 4; j++) ffma2(acc[i][j], asp, bp[j]);
            }
        }
        __syncthreads();
        av = av_n;
        bv = bv_n;
    }

#pragma unroll
    for (int i = 0; i < 8; i++) {
        int r = row0 + ty + i;
        if (r >= M) continue;
#pragma unroll
        for (int j = 0; j < 4; j++) {
            int c = col0 + tx + j * 2;
            if (c + 1 < N) {
                float2 v = unpack2(acc[i][j]);
                float o0 = v.x + bias[c];
                float o1 = v.y + bias[c + 1];
                if (relu) { o0 = fmaxf(o0, 0.f); o1 = fmaxf(o1, 0.f); }
                *(float2*)&C[(long long)r * N + c] = make_float2(o0, o1);
            }
        }
    }
}

// ---------------- CSR construction ----------------------------------------
__global__ void zero_cnt(int* cnt) {
    int i = blockIdx.x * blockDim.x + threadIdx.x;
    if (i < N_NODES) cnt[i] = 0;
}
__global__ void hist_rows(const int* __restrict__ row, int* cnt) {
    int i = blockIdx.x * blockDim.x + threadIdx.x;
    if (i < E_EDGES) atomicAdd(&cnt[row[i]], 1);
}
__global__ void exscan(const int* __restrict__ cnt, int* rowptr) {
    __shared__ int part[256];
    int t = threadIdx.x;
    int base = t * 40;
    int s = 0;
#pragma unroll
    for (int j = 0; j < 40; j++) {
        int idx = base + j;
        if (idx < N_NODES) s += cnt[idx];
    }
    part[t] = s;
    __syncthreads();
    for (int off = 1; off < 256; off <<= 1) {
        int v = (t >= off) ? part[t - off] : 0;
        __syncthreads();
        part[t] += v;
        __syncthreads();
    }
    int run = (t > 0) ? part[t - 1] : 0;
#pragma unroll
    for (int j = 0; j < 40; j++) {
        int idx = base + j;
        if (idx < N_NODES) { rowptr[idx] = run; run += cnt[idx]; }
    }
    if (t == 255) rowptr[N_NODES] = part[255];
}
__global__ void copy_cur(const int* __restrict__ rowptr, int* cur) {
    int i = blockIdx.x * blockDim.x + threadIdx.x;
    if (i < N_NODES) cur[i] = rowptr[i];
}
__global__ void scatter_csr(const int* __restrict__ row, const int* __restrict__ col,
                            const float* __restrict__ val, int* cur,
                            int* __restrict__ oc, float* __restrict__ ov) {
    int i = blockIdx.x * blockDim.x + threadIdx.x;
    if (i < E_EDGES) {
        int r = row[i];
        int p = atomicAdd(&cur[r], 1);
        oc[p] = col[i];
        ov[p] = val[i];
    }
}

// ---------------- fW softmax ([4][11]) -------------------------------------
__global__ void fw_softmax(const float* __restrict__ fw_rna,
                           const float* __restrict__ fw_atac, float* out) {
    int t = threadIdx.x;
    if (t >= 4) return;
    const float* src = (t < 2) ? (fw_rna + t * (K_HOPS + 1))
                               : (fw_atac + (t - 2) * (K_HOPS + 1));
    float m = -1e30f;
    for (int k = 0; k <= K_HOPS; k++) m = fmaxf(m, src[k]);
    float e[K_HOPS + 1];
    float s = 0.f;
    for (int k = 0; k <= K_HOPS; k++) { e[k] = expf(src[k] - m); s += e[k]; }
    float inv = 1.f / s;
    for (int k = 0; k <= K_HOPS; k++) out[t * (K_HOPS + 1) + k] = e[k] * inv;
}

// ---------------- acc init: acc[r, off+c] = w0 * h[r,c] (ld=512) -----------
__global__ void init_acc(const float* __restrict__ h, float* __restrict__ acc,
                         const float* __restrict__ wp) {
    int i = blockIdx.x * blockDim.x + threadIdx.x;  // float4 index over N*HID/4
    if (i >= N_NODES * HID / 4) return;
    float w = wp[0];
    int r = i >> 6;
    int c4 = i & 63;
    float4 v = ((const float4*)h)[i];
    float4 o = make_float4(w * v.x, w * v.y, w * v.z, w * v.w);
    ((float4*)(acc + (long long)r * 512))[c4] = o;
}

// ---------------- fused SpMM hop: xout = A@x ; acc += w*xout ---------------
// warp per row, H=256 split as 2 x float4 per lane
__global__ __launch_bounds__(256) void spmm_fused(
    const int* __restrict__ rowptr, const int* __restrict__ cols,
    const float* __restrict__ vals, const float* __restrict__ x,
    float* __restrict__ xout, float* __restrict__ acc,
    const float* __restrict__ wp)
{
    int r = blockIdx.x * 8 + (threadIdx.x >> 5);
    if (r >= N_NODES) return;
    int lane = threadIdx.x & 31;
    float w = wp[0];
    int e0 = rowptr[r], e1 = rowptr[r + 1];

    float4 s0 = make_float4(0.f, 0.f, 0.f, 0.f);
    float4 s1 = make_float4(0.f, 0.f, 0.f, 0.f);
    for (int e = e0; e < e1; e++) {
        int c = cols[e];
        float v = vals[e];
        const float4* xp = (const float4*)(x + (long long)c * HID);
        float4 a = xp[lane];
        float4 b = xp[lane + 32];
        s0.x += v * a.x; s0.y += v * a.y; s0.z += v * a.z; s0.w += v * a.w;
        s1.x += v * b.x; s1.y += v * b.y; s1.z += v * b.z; s1.w += v * b.w;
    }
    float4* xo = (float4*)(xout + (long long)r * HID);
    xo[lane] = s0;
    xo[lane + 32] = s1;
    float4* ap = (float4*)(acc + (long long)r * 512);
    float4 c0 = ap[lane];
    c0.x += w * s0.x; c0.y += w * s0.y; c0.z += w * s0.z; c0.w += w * s0.w;
    ap[lane] = c0;
    float4 c1 = ap[lane + 32];
    c1.x += w * s1.x; c1.y += w * s1.y; c1.z += w * s1.z; c1.w += w * s1.w;
    ap[lane + 32] = c1;
}

// ---------------- attention fusion: logits, softmax(2), mix ----------------
__global__ __launch_bounds__(256) void att_fuse(
    const float* __restrict__ zr, const float* __restrict__ za,
    const float* __restrict__ Wa, const float* __restrict__ ba,
    float* __restrict__ z, float* __restrict__ wout)
{
    int r = blockIdx.x * 8 + (threadIdx.x >> 5);
    if (r >= N_NODES) return;
    int lane = threadIdx.x & 31;
    const float* zrr = zr + (long long)r * HID;
    const float* zar = za + (long long)r * HID;

    float p0 = 0.f, p1 = 0.f;
    for (int c = lane; c < HID; c += 32) {
        float v = zrr[c];
        p0 += v * Wa[c * 2];
        p1 += v * Wa[c * 2 + 1];
        float u = zar[c];
        p0 += u * Wa[(HID + c) * 2];
        p1 += u * Wa[(HID + c) * 2 + 1];
    }
#pragma unroll
    for (int off = 16; off; off >>= 1) {
        p0 += __shfl_xor_sync(0xffffffffu, p0, off);
        p1 += __shfl_xor_sync(0xffffffffu, p1, off);
    }
    float l0 = p0 + ba[0], l1 = p1 + ba[1];
    float m = fmaxf(l0, l1);
    float e0 = expf(l0 - m), e1 = expf(l1 - m);
    float inv = 1.f / (e0 + e1);
    float w0 = e0 * inv, w1 = e1 * inv;
    if (lane == 0) {
        wout[r * 2 + 0] = w0;
        wout[r * 2 + 1] = w1;
    }
    for (int c = lane; c < HID; c += 32)
        z[(long long)r * HID + c] = w0 * zrr[c] + w1 * zar[c];
}

// ---------------- host orchestration ---------------------------------------
extern "C" void kernel_launch(void* const* d_in, const int* in_sizes, int n_in,
                              void* d_out, int out_size)
{
    const float* X_rna  = (const float*)d_in[0];
    const float* X_atac = (const float*)d_in[1];
    const int*   row1 = (const int*)d_in[2];
    const int*   col1 = (const int*)d_in[3];
    const float* val1 = (const float*)d_in[4];
    const int*   row2 = (const int*)d_in[5];
    const int*   col2 = (const int*)d_in[6];
    const float* val2 = (const float*)d_in[7];
    const float* Wi_rna  = (const float*)d_in[8];
    const float* bi_rna  = (const float*)d_in[9];
    const float* fW_rna  = (const float*)d_in[10];
    const float* Wo_rna  = (const float*)d_in[11];
    const float* bo_rna  = (const float*)d_in[12];
    const float* Wi_atac = (const float*)d_in[13];
    const float* bi_atac = (const float*)d_in[14];
    const float* fW_atac = (const float*)d_in[15];
    const float* Wo_atac = (const float*)d_in[16];
    const float* bo_atac = (const float*)d_in[17];
    const float* Wa = (const float*)d_in[18];
    const float* ba = (const float*)d_in[19];
    const float* Wd1_rna  = (const float*)d_in[20];
    const float* bd1_rna  = (const float*)d_in[21];
    const float* Wd2_rna  = (const float*)d_in[22];
    const float* bd2_rna  = (const float*)d_in[23];
    const float* Wd1_atac = (const float*)d_in[24];
    const float* bd1_atac = (const float*)d_in[25];
    const float* Wd2_atac = (const float*)d_in[26];
    const float* bd2_atac = (const float*)d_in[27];

    float* out = (float*)d_out;
    float* out_z     = out;
    float* out_zrna  = out + (size_t)N_NODES * HID;
    float* out_zatac = out + 2 * (size_t)N_NODES * HID;
    float* out_w     = out + 3 * (size_t)N_NODES * HID;
    float* out_rrec  = out_w + (size_t)N_NODES * 2;
    float* out_arec  = out_rrec + (size_t)N_NODES * D_RNA;

    float *ph, *pxk, *pzcat, *pt, *pfw, *pvals;
    int *prp, *pcols, *pcnt, *pcur;
    cudaGetSymbolAddress((void**)&ph, g_h);
    cudaGetSymbolAddress((void**)&pxk, g_xk);
    cudaGetSymbolAddress((void**)&pzcat, g_zcat);
    cudaGetSymbolAddress((void**)&pt, g_t);
    cudaGetSymbolAddress((void**)&pfw, g_fw);
    cudaGetSymbolAddress((void**)&prp, g_rowptr);
    cudaGetSymbolAddress((void**)&pcols, g_cols);
    cudaGetSymbolAddress((void**)&pvals, g_vals);
    cudaGetSymbolAddress((void**)&pcnt, g_cnt);
    cudaGetSymbolAddress((void**)&pcur, g_cur);

    // 1. softmax the hop-weight logits
    fw_softmax<<<1, 32>>>(fW_rna, fW_atac, pfw);

    // 2. build CSR for both orders
    for (int o = 0; o < 2; o++) {
        const int* rw = o ? row2 : row1;
        const int* cl = o ? col2 : col1;
        const float* vl = o ? val2 : val1;
        int* cnt = pcnt + o * N_NODES;
        int* cur = pcur + o * N_NODES;
        int* rp  = prp + o * (N_NODES + 1);
        int* oc  = pcols + o * E_EDGES;
        float* ov = pvals + o * E_EDGES;
        zero_cnt<<<40, 256>>>(cnt);
        hist_rows<<<1250, 256>>>(rw, cnt);
        exscan<<<1, 256>>>(cnt, rp);
        copy_cur<<<40, 256>>>(rp, cur);
        scatter_csr<<<1250, 256>>>(rw, cl, vl, cur, oc, ov);
    }

    const dim3 g256(2, 79);  // N=256 tiles x M tiles

    // 3. encoders
    for (int enc = 0; enc < 2; enc++) {
        const float* X  = enc ? X_atac : X_rna;
        const int    D  = enc ? D_ATAC : D_RNA;
        const float* Wi = enc ? Wi_atac : Wi_rna;
        const float* bi = enc ? bi_atac : bi_rna;
        const float* Wo = enc ? Wo_atac : Wo_rna;
        const float* bo = enc ? bo_atac : bo_rna;
        float* zout = enc ? out_zatac : out_zrna;

        for (int o = 0; o < 2; o++) {
            sgemm_bias<<<g256, 256>>>(X, Wi + (size_t)o * D * HID, bi + o * HID,
                                      ph, N_NODES, HID, D, 0);
            const float* wrow = pfw + (enc * 2 + o) * (K_HOPS + 1);
            init_acc<<<2500, 256>>>(ph, pzcat + o * HID, wrow);
            float* bufs[2] = {ph, pxk};
            for (int k = 1; k <= K_HOPS; k++) {
                float* xin  = bufs[(k + 1) & 1];
                float* xout = bufs[k & 1];
                spmm_fused<<<1250, 256>>>(prp + o * (N_NODES + 1),
                                          pcols + o * E_EDGES, pvals + o * E_EDGES,
                                          xin, xout, pzcat + o * HID, wrow + k);
            }
        }
        sgemm_bias<<<g256, 256>>>(pzcat, Wo, bo, zout, N_NODES, HID, 2 * HID, 0);
    }

    // 4. attention fusion -> z, weight
    att_fuse<<<1250, 256>>>(out_zrna, out_zatac, Wa, ba, out_z, out_w);

    // 5. decoders
    sgemm_bias<<<g256, 256>>>(out_z, Wd1_rna, bd1_rna, pt, N_NODES, HID, HID, 1);
    sgemm_bias<<<dim3(16, 79), 256>>>(pt, Wd2_rna, bd2_rna, out_rrec,
                                      N_NODES, D_RNA, HID, 0);
    sgemm_bias<<<g256, 256>>>(out_z, Wd1_atac, bd1_atac, pt, N_NODES, HID, HID, 1);
    sgemm_bias<<<dim3(40, 79), 256>>>(pt, Wd2_atac, bd2_atac, out_arec,
                                      N_NODES, D_ATAC, HID, 0);
}

// round 3
// speedup vs baseline: 1.5919x; 1.5919x over previous
#include <cuda_runtime.h>
#include <cuda_bf16.h>
#include <cstdint>

#define N_NODES 10000
#define E_EDGES 320000
#define HID 256
#define K_HOPS 10
#define D_RNA 2000
#define D_ATAC 5000

// ---------------- scratch (static device allocations; no cudaMalloc) -------
__device__ float g_h[N_NODES * HID];
__device__ float g_xk[N_NODES * HID];
__device__ float g_zcat[N_NODES * 2 * HID];
__device__ float g_t[N_NODES * HID];
__device__ float g_fw[4 * (K_HOPS + 1)];
__device__ int   g_rowptr[2 * (N_NODES + 1)];
__device__ int   g_cols[2 * E_EDGES];
__device__ float g_vals[2 * E_EDGES];
__device__ int   g_cnt[2 * N_NODES];
__device__ int   g_cur[2 * N_NODES];
// split-bf16 concat-K operand buffers
__device__ __nv_bfloat16 g_acat[(size_t)N_NODES * 15008];
__device__ __nv_bfloat16 g_acat2[(size_t)N_NODES * 768];
__device__ __nv_bfloat16 g_bcat[3900000];

// ================= split-bf16 conversion kernels ===========================
// A fp32 [M,K] -> out bf16 [M, Kcp], segments (hi | lo | hi).
__global__ void conv_a(const float* __restrict__ A, __nv_bfloat16* __restrict__ out,
                       int M, int K, int Kcp)
{
    int kh = K >> 1;
    int total = M * kh;
    for (int i = blockIdx.x * blockDim.x + threadIdx.x; i < total;
         i += gridDim.x * blockDim.x) {
        int m = i / kh;
        int k = (i - m * kh) * 2;
        float2 x = *(const float2*)(A + (size_t)m * K + k);
        __nv_bfloat16 h0 = __float2bfloat16(x.x);
        __nv_bfloat16 h1 = __float2bfloat16(x.y);
        __nv_bfloat16 l0 = __float2bfloat16(x.x - __bfloat162float(h0));
        __nv_bfloat16 l1 = __float2bfloat16(x.y - __bfloat162float(h1));
        __nv_bfloat162 hp; hp.x = h0; hp.y = h1;
        __nv_bfloat162 lp; lp.x = l0; lp.y = l1;
        size_t base = (size_t)m * Kcp + k;
        *(__nv_bfloat162*)(out + base) = hp;
        *(__nv_bfloat162*)(out + base + K) = lp;
        *(__nv_bfloat162*)(out + base + 2 * K) = hp;
    }
}

__global__ void pad_a(__nv_bfloat16* out, int M, int Kcp, int start)
{
    int w = Kcp - start;
    int total = M * w;
    for (int i = blockIdx.x * blockDim.x + threadIdx.x; i < total;
         i += gridDim.x * blockDim.x) {
        int m = i / w;
        int j = i - m * w;
        out[(size_t)m * Kcp + start + j] = __float2bfloat16(0.f);
    }
}

// B fp32 [K,N] -> out bf16 [Kcp, N], row segments (hi ; hi ; lo).
__global__ void conv_b(const float* __restrict__ B, __nv_bfloat16* __restrict__ out,
                       int K, int N, int Kcp)
{
    int nh = N >> 1;
    int total = K * nh;
    for (int i = blockIdx.x * blockDim.x + threadIdx.x; i < total;
         i += gridDim.x * blockDim.x) {
        int k = i / nh;
        int n = (i - k * nh) * 2;
        float2 x = *(const float2*)(B + (size_t)k * N + n);
        __nv_bfloat16 h0 = __float2bfloat16(x.x);
        __nv_bfloat16 h1 = __float2bfloat16(x.y);
        __nv_bfloat16 l0 = __float2bfloat16(x.x - __bfloat162float(h0));
        __nv_bfloat16 l1 = __float2bfloat16(x.y - __bfloat162float(h1));
        __nv_bfloat162 hp; hp.x = h0; hp.y = h1;
        __nv_bfloat162 lp; lp.x = l0; lp.y = l1;
        *(__nv_bfloat162*)(out + (size_t)k * N + n) = hp;
        *(__nv_bfloat162*)(out + (size_t)(K + k) * N + n) = hp;
        *(__nv_bfloat162*)(out + (size_t)(2 * K + k) * N + n) = lp;
    }
}

__global__ void pad_b(__nv_bfloat16* out, int count)
{
    for (int i = blockIdx.x * blockDim.x + threadIdx.x; i < count;
         i += gridDim.x * blockDim.x)
        out[i] = __float2bfloat16(0.f);
}

// ================= bf16 tensor-core GEMM ===================================
__device__ __forceinline__ void cpa16(void* sm, const void* gm, bool p)
{
    unsigned int s = (unsigned int)__cvta_generic_to_shared(sm);
    int sz = p ? 16 : 0;
    asm volatile("cp.async.cg.shared.global [%0], [%1], 16, %2;"
                 :: "r"(s), "l"(gm), "r"(sz) : "memory");
}
__device__ __forceinline__ void ldsm4(unsigned int* d, const void* p)
{
    unsigned int s = (unsigned int)__cvta_generic_to_shared(p);
    asm volatile("ldmatrix.sync.aligned.m8n8.x4.shared.b16 {%0,%1,%2,%3}, [%4];"
                 : "=r"(d[0]), "=r"(d[1]), "=r"(d[2]), "=r"(d[3]) : "r"(s));
}
__device__ __forceinline__ void ldsm4t(unsigned int* d, const void* p)
{
    unsigned int s = (unsigned int)__cvta_generic_to_shared(p);
    asm volatile("ldmatrix.sync.aligned.m8n8.x4.trans.shared.b16 {%0,%1,%2,%3}, [%4];"
                 : "=r"(d[0]), "=r"(d[1]), "=r"(d[2]), "=r"(d[3]) : "r"(s));
}
__device__ __forceinline__ void mma16816(float* c, const unsigned int* a,
                                         unsigned int b0, unsigned int b1)
{
    asm volatile("mma.sync.aligned.m16n8k16.row.col.f32.bf16.bf16.f32 "
                 "{%0,%1,%2,%3}, {%4,%5,%6,%7}, {%8,%9}, {%0,%1,%2,%3};"
                 : "+f"(c[0]), "+f"(c[1]), "+f"(c[2]), "+f"(c[3])
                 : "r"(a[0]), "r"(a[1]), "r"(a[2]), "r"(a[3]), "r"(b0), "r"(b1));
}

// C[M,N] = A[M,Kc] @ B[Kc,N] + bias (opt relu). Kc multiple of 32, N even.
// 128x128x32 block tile, 8 warps (2x4), warp tile 64x32, 2-stage cp.async.
__global__ __launch_bounds__(256, 2) void gemm_bf16(
    const __nv_bfloat16* __restrict__ A, const __nv_bfloat16* __restrict__ B,
    const float* __restrict__ bias, float* __restrict__ C,
    int M, int N, int Kc, int relu)
{
    __shared__ __nv_bfloat16 As[2][128][40];
    __shared__ __nv_bfloat16 Bs[2][32][136];

    const int tid = threadIdx.x;
    const int lane = tid & 31;
    const int warp = tid >> 5;
    const int wm = warp >> 2;
    const int wn = warp & 3;
    const int row0 = blockIdx.y * 128;
    const int col0 = blockIdx.x * 128;

    const int ar = tid >> 1;
    const int ac = (tid & 1) << 4;
    const int arow = row0 + ar;
    const bool apred = arow < M;
    const __nv_bfloat16* Abase = A + (size_t)(apred ? arow : 0) * Kc + ac;

    const int br = tid >> 3;
    const int bc = (tid & 7) << 4;
    const int bcol = col0 + bc;
    const bool bp0 = bcol < N;
    const bool bp1 = (bcol + 8) < N;
    const int bc0 = bp0 ? bcol : 0;
    const int bc1 = bp1 ? (bcol + 8) : 0;

    float acc[4][4][4];
#pragma unroll
    for (int i = 0; i < 4; i++) {
#pragma unroll
        for (int j = 0; j < 4; j++) {
#pragma unroll
            for (int q = 0; q < 4; q++) acc[i][j][q] = 0.f;
        }
    }

    const int iters = Kc >> 5;

    cpa16(&As[0][ar][ac], Abase, apred);
    cpa16(&As[0][ar][ac + 8], Abase + 8, apred);
    {
        const __nv_bfloat16* Bb = B + (size_t)br * N;
        cpa16(&Bs[0][br][bc], Bb + bc0, bp0);
        cpa16(&Bs[0][br][bc + 8], Bb + bc1, bp1);
    }
    asm volatile("cp.async.commit_group;" ::: "memory");

    int s = 0;
    for (int it = 0; it < iters; it++) {
        if (it + 1 < iters) {
            const int kk = (it + 1) << 5;
            cpa16(&As[s ^ 1][ar][ac], Abase + kk, apred);
            cpa16(&As[s ^ 1][ar][ac + 8], Abase + kk + 8, apred);
            const __nv_bfloat16* Bb = B + (size_t)(kk + br) * N;
            cpa16(&Bs[s ^ 1][br][bc], Bb + bc0, bp0);
            cpa16(&Bs[s ^ 1][br][bc + 8], Bb + bc1, bp1);
            asm volatile("cp.async.commit_group;" ::: "memory");
            asm volatile("cp.async.wait_group 1;" ::: "memory");
        } else {
            asm volatile("cp.async.wait_group 0;" ::: "memory");
        }
        __syncthreads();

#pragma unroll
        for (int k16 = 0; k16 < 2; k16++) {
            unsigned int af[4][4];
#pragma unroll
            for (int mi = 0; mi < 4; mi++) {
                ldsm4(af[mi], &As[s][wm * 64 + mi * 16 + (lane & 15)]
                                    [k16 * 16 + ((lane >> 4) << 3)]);
            }
            unsigned int bfr[2][4];
#pragma unroll
            for (int g = 0; g < 2; g++) {
                ldsm4t(bfr[g], &Bs[s][k16 * 16 + (lane & 15)]
                                     [wn * 32 + g * 16 + ((lane >> 4) << 3)]);
            }
#pragma unroll
            for (int mi = 0; mi < 4; mi++) {
#pragma unroll
                for (int ni = 0; ni < 4; ni++) {
                    mma16816(acc[mi][ni], af[mi],
                             bfr[ni >> 1][(ni & 1) * 2],
                             bfr[ni >> 1][(ni & 1) * 2 + 1]);
                }
            }
        }
        __syncthreads();
        s ^= 1;
    }

#pragma unroll
    for (int mi = 0; mi < 4; mi++) {
        int r = row0 + wm * 64 + mi * 16 + (lane >> 2);
#pragma unroll
        for (int ni = 0; ni < 4; ni++) {
            int c = col0 + wn * 32 + ni * 8 + ((lane & 3) << 1);
            if (c < N) {
                float b0 = bias[c];
                float b1 = bias[c + 1];
                if (r < M) {
                    float o0 = acc[mi][ni][0] + b0;
                    float o1 = acc[mi][ni][1] + b1;
                    if (relu) { o0 = fmaxf(o0, 0.f); o1 = fmaxf(o1, 0.f); }
                    *(float2*)(C + (size_t)r * N + c) = make_float2(o0, o1);
                }
                if (r + 8 < M) {
                    float o2 = acc[mi][ni][2] + b0;
                    float o3 = acc[mi][ni][3] + b1;
                    if (relu) { o2 = fmaxf(o2, 0.f); o3 = fmaxf(o3, 0.f); }
                    *(float2*)(C + (size_t)(r + 8) * N + c) = make_float2(o2, o3);
                }
            }
        }
    }
}

// ================= CSR construction ========================================
__global__ void zero_cnt(int* cnt)
{
    int i = blockIdx.x * blockDim.x + threadIdx.x;
    if (i < N_NODES) cnt[i] = 0;
}
__global__ void hist_rows(const int* __restrict__ row, int* cnt)
{
    int i = blockIdx.x * blockDim.x + threadIdx.x;
    if (i < E_EDGES) atomicAdd(&cnt[row[i]], 1);
}
__global__ void exscan(const int* __restrict__ cnt, int* rowptr)
{
    __shared__ int part[256];
    int t = threadIdx.x;
    int base = t * 40;
    int s = 0;
#pragma unroll
    for (int j = 0; j < 40; j++) {
        int idx = base + j;
        if (idx < N_NODES) s += cnt[idx];
    }
    part[t] = s;
    __syncthreads();
    for (int off = 1; off < 256; off <<= 1) {
        int v = (t >= off) ? part[t - off] : 0;
        __syncthreads();
        part[t] += v;
        __syncthreads();
    }
    int run = (t > 0) ? part[t - 1] : 0;
#pragma unroll
    for (int j = 0; j < 40; j++) {
        int idx = base + j;
        if (idx < N_NODES) { rowptr[idx] = run; run += cnt[idx]; }
    }
    if (t == 255) rowptr[N_NODES] = part[255];
}
__global__ void copy_cur(const int* __restrict__ rowptr, int* cur)
{
    int i = blockIdx.x * blockDim.x + threadIdx.x;
    if (i < N_NODES) cur[i] = rowptr[i];
}
__global__ void scatter_csr(const int* __restrict__ row, const int* __restrict__ col,
                            const float* __restrict__ val, int* cur,
                            int* __restrict__ oc, float* __restrict__ ov)
{
    int i = blockIdx.x * blockDim.x + threadIdx.x;
    if (i < E_EDGES) {
        int r = row[i];
        int p = atomicAdd(&cur[r], 1);
        oc[p] = col[i];
        ov[p] = val[i];
    }
}

// ================= fW softmax ==============================================
__global__ void fw_softmax(const float* __restrict__ fw_rna,
                           const float* __restrict__ fw_atac, float* out)
{
    int t = threadIdx.x;
    if (t >= 4) return;
    const float* src = (t < 2) ? (fw_rna + t * (K_HOPS + 1))
                               : (fw_atac + (t - 2) * (K_HOPS + 1));
    float m = -1e30f;
    for (int k = 0; k <= K_HOPS; k++) m = fmaxf(m, src[k]);
    float e[K_HOPS + 1];
    float s = 0.f;
    for (int k = 0; k <= K_HOPS; k++) { e[k] = expf(src[k] - m); s += e[k]; }
    float inv = 1.f / s;
    for (int k = 0; k <= K_HOPS; k++) out[t * (K_HOPS + 1) + k] = e[k] * inv;
}

// ================= propagation =============================================
__global__ void init_acc(const float* __restrict__ h, float* __restrict__ acc,
                         const float* __restrict__ wp)
{
    int i = blockIdx.x * blockDim.x + threadIdx.x;
    if (i >= N_NODES * HID / 4) return;
    float w = wp[0];
    int r = i >> 6;
    int c4 = i & 63;
    float4 v = ((const float4*)h)[i];
    float4 o = make_float4(w * v.x, w * v.y, w * v.z, w * v.w);
    ((float4*)(acc + (long long)r * 512))[c4] = o;
}

__global__ __launch_bounds__(256) void spmm_fused(
    const int* __restrict__ rowptr, const int* __restrict__ cols,
    const float* __restrict__ vals, const float* __restrict__ x,
    float* __restrict__ xout, float* __restrict__ acc,
    const float* __restrict__ wp)
{
    int r = blockIdx.x * 8 + (threadIdx.x >> 5);
    if (r >= N_NODES) return;
    int lane = threadIdx.x & 31;
    float w = wp[0];
    int e0 = rowptr[r];
    int e1 = rowptr[r + 1];

    float4 s0 = make_float4(0.f, 0.f, 0.f, 0.f);
    float4 s1 = make_float4(0.f, 0.f, 0.f, 0.f);
    for (int e = e0; e < e1; e++) {
        int c = cols[e];
        float v = vals[e];
        const float4* xp = (const float4*)(x + (long long)c * HID);
        float4 a = xp[lane];
        float4 b = xp[lane + 32];
        s0.x += v * a.x; s0.y += v * a.y; s0.z += v * a.z; s0.w += v * a.w;
        s1.x += v * b.x; s1.y += v * b.y; s1.z += v * b.z; s1.w += v * b.w;
    }
    float4* xo = (float4*)(xout + (long long)r * HID);
    xo[lane] = s0;
    xo[lane + 32] = s1;
    float4* ap = (float4*)(acc + (long long)r * 512);
    float4 c0 = ap[lane];
    c0.x += w * s0.x; c0.y += w * s0.y; c0.z += w * s0.z; c0.w += w * s0.w;
    ap[lane] = c0;
    float4 c1 = ap[lane + 32];
    c1.x += w * s1.x; c1.y += w * s1.y; c1.z += w * s1.z; c1.w += w * s1.w;
    ap[lane + 32] = c1;
}

// ================= attention fusion ========================================
__global__ __launch_bounds__(256) void att_fuse(
    const float* __restrict__ zr, const float* __restrict__ za,
    const float* __restrict__ Wa, const float* __restrict__ ba,
    float* __restrict__ z, float* __restrict__ wout)
{
    int r = blockIdx.x * 8 + (threadIdx.x >> 5);
    if (r >= N_NODES) return;
    int lane = threadIdx.x & 31;
    const float* zrr = zr + (long long)r * HID;
    const float* zar = za + (long long)r * HID;

    float p0 = 0.f;
    float p1 = 0.f;
    for (int c = lane; c < HID; c += 32) {
        float v = zrr[c];
        p0 += v * Wa[c * 2];
        p1 += v * Wa[c * 2 + 1];
        float u = zar[c];
        p0 += u * Wa[(HID + c) * 2];
        p1 += u * Wa[(HID + c) * 2 + 1];
    }
#pragma unroll
    for (int off = 16; off; off >>= 1) {
        p0 += __shfl_xor_sync(0xffffffffu, p0, off);
        p1 += __shfl_xor_sync(0xffffffffu, p1, off);
    }
    float l0 = p0 + ba[0];
    float l1 = p1 + ba[1];
    float m = fmaxf(l0, l1);
    float e0 = expf(l0 - m);
    float e1 = expf(l1 - m);
    float inv = 1.f / (e0 + e1);
    float w0 = e0 * inv;
    float w1 = e1 * inv;
    if (lane == 0) {
        wout[r * 2 + 0] = w0;
        wout[r * 2 + 1] = w1;
    }
    for (int c = lane; c < HID; c += 32)
        z[(long long)r * HID + c] = w0 * zrr[c] + w1 * zar[c];
}

// ================= host orchestration ======================================
static inline int cgrid(long long total, int tpb)
{
    long long b = (total + tpb - 1) / tpb;
    if (b > 65535) b = 65535;
    return (int)b;
}

extern "C" void kernel_launch(void* const* d_in, const int* in_sizes, int n_in,
                              void* d_out, int out_size)
{
    const float* X_rna  = (const float*)d_in[0];
    const float* X_atac = (const float*)d_in[1];
    const int*   row1 = (const int*)d_in[2];
    const int*   col1 = (const int*)d_in[3];
    const float* val1 = (const float*)d_in[4];
    const int*   row2 = (const int*)d_in[5];
    const int*   col2 = (const int*)d_in[6];
    const float* val2 = (const float*)d_in[7];
    const float* Wi_rna  = (const float*)d_in[8];
    const float* bi_rna  = (const float*)d_in[9];
    const float* fW_rna  = (const float*)d_in[10];
    const float* Wo_rna  = (const float*)d_in[11];
    const float* bo_rna  = (const float*)d_in[12];
    const float* Wi_atac = (const float*)d_in[13];
    const float* bi_atac = (const float*)d_in[14];
    const float* fW_atac = (const float*)d_in[15];
    const float* Wo_atac = (const float*)d_in[16];
    const float* bo_atac = (const float*)d_in[17];
    const float* Wa = (const float*)d_in[18];
    const float* ba = (const float*)d_in[19];
    const float* Wd1_rna  = (const float*)d_in[20];
    const float* bd1_rna  = (const float*)d_in[21];
    const float* Wd2_rna  = (const float*)d_in[22];
    const float* bd2_rna  = (const float*)d_in[23];
    const float* Wd1_atac = (const float*)d_in[24];
    const float* bd1_atac = (const float*)d_in[25];
    const float* Wd2_atac = (const float*)d_in[26];
    const float* bd2_atac = (const float*)d_in[27];

    float* out = (float*)d_out;
    float* out_z     = out;
    float* out_zrna  = out + (size_t)N_NODES * HID;
    float* out_zatac = out + 2 * (size_t)N_NODES * HID;
    float* out_w     = out + 3 * (size_t)N_NODES * HID;
    float* out_rrec  = out_w + (size_t)N_NODES * 2;
    float* out_arec  = out_rrec + (size_t)N_NODES * D_RNA;

    float* ph = 0;
    float* pxk = 0;
    float* pzcat = 0;
    float* pt = 0;
    float* pfw = 0;
    float* pvals = 0;
    int* prp = 0;
    int* pcols = 0;
    int* pcnt = 0;
    int* pcur = 0;
    __nv_bfloat16* pac = 0;
    __nv_bfloat16* pac2 = 0;
    __nv_bfloat16* pbc = 0;
    cudaGetSymbolAddress((void**)&ph, g_h);
    cudaGetSymbolAddress((void**)&pxk, g_xk);
    cudaGetSymbolAddress((void**)&pzcat, g_zcat);
    cudaGetSymbolAddress((void**)&pt, g_t);
    cudaGetSymbolAddress((void**)&pfw, g_fw);
    cudaGetSymbolAddress((void**)&prp, g_rowptr);
    cudaGetSymbolAddress((void**)&pcols, g_cols);
    cudaGetSymbolAddress((void**)&pvals, g_vals);
    cudaGetSymbolAddress((void**)&pcnt, g_cnt);
    cudaGetSymbolAddress((void**)&pcur, g_cur);
    cudaGetSymbolAddress((void**)&pac, g_acat);
    cudaGetSymbolAddress((void**)&pac2, g_acat2);
    cudaGetSymbolAddress((void**)&pbc, g_bcat);

    // 1. softmax the hop-weight logits
    fw_softmax<<<1, 32>>>(fW_rna, fW_atac, pfw);

    // 2. build CSR for both orders
    for (int o = 0; o < 2; o++) {
        const int* rw = o ? row2 : row1;
        const int* cl = o ? col2 : col1;
        const float* vl = o ? val2 : val1;
        int* cnt = pcnt + o * N_NODES;
        int* cur = pcur + o * N_NODES;
        int* rp  = prp + o * (N_NODES + 1);
        int* oc  = pcols + o * E_EDGES;
        float* ov = pvals + o * E_EDGES;
        zero_cnt<<<40, 256>>>(cnt);
        hist_rows<<<1250, 256>>>(rw, cnt);
        exscan<<<1, 256>>>(cnt, rp);
        copy_cur<<<40, 256>>>(rp, cur);
        scatter_csr<<<1250, 256>>>(rw, cl, vl, cur, oc, ov);
    }

    const dim3 gH(2, 79);
    const int TPB = 256;

    // 3. encoders
    for (int enc = 0; enc < 2; enc++) {
        const float* X  = enc ? X_atac : X_rna;
        const int    D  = enc ? D_ATAC : D_RNA;
        const int    Kcp = enc ? 15008 : 6016;
        const float* Wi = enc ? Wi_atac : Wi_rna;
        const float* bi = enc ? bi_atac : bi_rna;
        const float* Wo = enc ? Wo_atac : Wo_rna;
        const float* bo = enc ? bo_atac : bo_rna;
        float* zout = enc ? out_zatac : out_zrna;

        conv_a<<<cgrid((long long)N_NODES * D / 2, TPB), TPB>>>(X, pac, N_NODES, D, Kcp);
        pad_a<<<cgrid((long long)N_NODES * (Kcp - 3 * D), TPB), TPB>>>(pac, N_NODES, Kcp, 3 * D);

        for (int o = 0; o < 2; o++) {
            conv_b<<<cgrid((long long)D * HID / 2, TPB), TPB>>>(
                Wi + (size_t)o * D * HID, pbc, D, HID, Kcp);
            pad_b<<<cgrid((long long)(Kcp - 3 * D) * HID, TPB), TPB>>>(
                pbc + (size_t)3 * D * HID, (Kcp - 3 * D) * HID);
            gemm_bf16<<<gH, 256>>>(pac, pbc, bi + o * HID, ph, N_NODES, HID, Kcp, 0);

            const float* wrow = pfw + (enc * 2 + o) * (K_HOPS + 1);
            init_acc<<<2500, 256>>>(ph, pzcat + o * HID, wrow);
            float* bufs[2] = {ph, pxk};
            for (int k = 1; k <= K_HOPS; k++) {
                float* xin  = bufs[(k + 1) & 1];
                float* xout = bufs[k & 1];
                spmm_fused<<<1250, 256>>>(prp + o * (N_NODES + 1),
                                          pcols + o * E_EDGES, pvals + o * E_EDGES,
                                          xin, xout, pzcat + o * HID, wrow + k);
            }
        }
        conv_a<<<cgrid((long long)N_NODES * 512 / 2, TPB), TPB>>>(pzcat, pac, N_NODES, 512, 1536);
        conv_b<<<cgrid((long long)512 * HID / 2, TPB), TPB>>>(Wo, pbc, 512, HID, 1536);
        gemm_bf16<<<gH, 256>>>(pac, pbc, bo, zout, N_NODES, HID, 1536, 0);
    }

    // 4. attention fusion -> z, weight
    att_fuse<<<1250, 256>>>(out_zrna, out_zatac, Wa, ba, out_z, out_w);

    // 5. decoders
    conv_a<<<cgrid((long long)N_NODES * HID / 2, TPB), TPB>>>(out_z, pac, N_NODES, HID, 768);

    conv_b<<<cgrid((long long)HID * HID / 2, TPB), TPB>>>(Wd1_rna, pbc, HID, HID, 768);
    gemm_bf16<<<gH, 256>>>(pac, pbc, bd1_rna, pt, N_NODES, HID, 768, 1);
    conv_a<<<cgrid((long long)N_NODES * HID / 2, TPB), TPB>>>(pt, pac2, N_NODES, HID, 768);
    conv_b<<<cgrid((long long)HID * D_RNA / 2, TPB), TPB>>>(Wd2_rna, pbc, HID, D_RNA, 768);
    gemm_bf16<<<dim3(16, 79), 256>>>(pac2, pbc, bd2_rna, out_rrec, N_NODES, D_RNA, 768, 0);

    conv_b<<<cgrid((long long)HID * HID / 2, TPB), TPB>>>(Wd1_atac, pbc, HID, HID, 768);
    gemm_bf16<<<gH, 256>>>(pac, pbc, bd1_atac, pt, N_NODES, HID, 768, 1);
    conv_a<<<cgrid((long long)N_NODES * HID / 2, TPB), TPB>>>(pt, pac2, N_NODES, HID, 768);
    conv_b<<<cgrid((long long)HID * D_ATAC / 2, TPB), TPB>>>(Wd2_atac, pbc, HID, D_ATAC, 768);
    gemm_bf16<<<dim3(40, 79), 256>>>(pac2, pbc, bd2_atac, out_arec, N_NODES, D_ATAC, 768, 0);
}

// round 4
// speedup vs baseline: 2.1715x; 1.3641x over previous
#include <cuda_runtime.h>
#include <cuda_bf16.h>
#include <cstdint>

#define N_NODES 10000
#define E_EDGES 320000
#define HID 256
#define K_HOPS 10
#define D_RNA 2000
#define D_ATAC 5000

// ---------------- scratch (static device allocations; no cudaMalloc) -------
__device__ float g_b0[N_NODES * HID];
__device__ float g_b1[N_NODES * HID];
__device__ float g_b2[N_NODES * HID];
__device__ float g_b3[N_NODES * HID];
__device__ float g_b4[N_NODES * HID];
__device__ float g_zcr[N_NODES * 2 * HID];
__device__ float g_zca[N_NODES * 2 * HID];
__device__ float g_fw[4 * (K_HOPS + 1)];
__device__ int   g_rowptr[2 * (N_NODES + 1)];
__device__ int   g_cols[2 * E_EDGES];
__device__ float g_vals[2 * E_EDGES];
__device__ int   g_cnt[2 * N_NODES];
__device__ int   g_cur[2 * N_NODES];
// split-bf16 operand buffers
__device__ __nv_bfloat16 g_acat[(size_t)N_NODES * 15008];
__device__ __nv_bfloat16 g_awor[(size_t)N_NODES * 1536];
__device__ __nv_bfloat16 g_awoa[(size_t)N_NODES * 1536];
__device__ __nv_bfloat16 g_az[(size_t)N_NODES * 768];
__device__ __nv_bfloat16 g_adr[(size_t)N_NODES * 768];
__device__ __nv_bfloat16 g_ada[(size_t)N_NODES * 768];
__device__ __nv_bfloat16 g_bwir0[6016 * 256];
__device__ __nv_bfloat16 g_bwir1[6016 * 256];
__device__ __nv_bfloat16 g_bwia0[15008 * 256];
__device__ __nv_bfloat16 g_bwia1[15008 * 256];
__device__ __nv_bfloat16 g_bwor[1536 * 256];
__device__ __nv_bfloat16 g_bwoa[1536 * 256];
__device__ __nv_bfloat16 g_bd1r[768 * 256];
__device__ __nv_bfloat16 g_bd1a[768 * 256];
__device__ __nv_bfloat16 g_bd2r[768 * 2000];
__device__ __nv_bfloat16 g_bd2a[768 * 5000];

// ================= split-bf16 conversion kernels ===========================
__global__ void conv_a(const float* __restrict__ A, __nv_bfloat16* __restrict__ out,
                       int M, int K, int Kcp)
{
    int kh = K >> 1;
    int total = M * kh;
    for (int i = blockIdx.x * blockDim.x + threadIdx.x; i < total;
         i += gridDim.x * blockDim.x) {
        int m = i / kh;
        int k = (i - m * kh) * 2;
        float2 x = *(const float2*)(A + (size_t)m * K + k);
        __nv_bfloat16 h0 = __float2bfloat16(x.x);
        __nv_bfloat16 h1 = __float2bfloat16(x.y);
        __nv_bfloat16 l0 = __float2bfloat16(x.x - __bfloat162float(h0));
        __nv_bfloat16 l1 = __float2bfloat16(x.y - __bfloat162float(h1));
        __nv_bfloat162 hp; hp.x = h0; hp.y = h1;
        __nv_bfloat162 lp; lp.x = l0; lp.y = l1;
        size_t base = (size_t)m * Kcp + k;
        *(__nv_bfloat162*)(out + base) = hp;
        *(__nv_bfloat162*)(out + base + K) = lp;
        *(__nv_bfloat162*)(out + base + 2 * K) = hp;
    }
}

__global__ void pad_a(__nv_bfloat16* out, int M, int Kcp, int start)
{
    int w = Kcp - start;
    int total = M * w;
    for (int i = blockIdx.x * blockDim.x + threadIdx.x; i < total;
         i += gridDim.x * blockDim.x) {
        int m = i / w;
        int j = i - m * w;
        out[(size_t)m * Kcp + start + j] = __float2bfloat16(0.f);
    }
}

__global__ void conv_b(const float* __restrict__ B, __nv_bfloat16* __restrict__ out,
                       int K, int N)
{
    int nh = N >> 1;
    int total = K * nh;
    for (int i = blockIdx.x * blockDim.x + threadIdx.x; i < total;
         i += gridDim.x * blockDim.x) {
        int k = i / nh;
        int n = (i - k * nh) * 2;
        float2 x = *(const float2*)(B + (size_t)k * N + n);
        __nv_bfloat16 h0 = __float2bfloat16(x.x);
        __nv_bfloat16 h1 = __float2bfloat16(x.y);
        __nv_bfloat16 l0 = __float2bfloat16(x.x - __bfloat162float(h0));
        __nv_bfloat16 l1 = __float2bfloat16(x.y - __bfloat162float(h1));
        __nv_bfloat162 hp; hp.x = h0; hp.y = h1;
        __nv_bfloat162 lp; lp.x = l0; lp.y = l1;
        *(__nv_bfloat162*)(out + (size_t)k * N + n) = hp;
        *(__nv_bfloat162*)(out + (size_t)(K + k) * N + n) = hp;
        *(__nv_bfloat162*)(out + (size_t)(2 * K + k) * N + n) = lp;
    }
}

__global__ void pad_b(__nv_bfloat16* out, int count)
{
    for (int i = blockIdx.x * blockDim.x + threadIdx.x; i < count;
         i += gridDim.x * blockDim.x)
        out[i] = __float2bfloat16(0.f);
}

// ================= bf16 tensor-core GEMM ===================================
__device__ __forceinline__ void cpa16(void* sm, const void* gm, bool p)
{
    unsigned int s = (unsigned int)__cvta_generic_to_shared(sm);
    int sz = p ? 16 : 0;
    asm volatile("cp.async.cg.shared.global [%0], [%1], 16, %2;"
                 :: "r"(s), "l"(gm), "r"(sz) : "memory");
}
__device__ __forceinline__ void ldsm4(unsigned int* d, const void* p)
{
    unsigned int s = (unsigned int)__cvta_generic_to_shared(p);
    asm volatile("ldmatrix.sync.aligned.m8n8.x4.shared.b16 {%0,%1,%2,%3}, [%4];"
                 : "=r"(d[0]), "=r"(d[1]), "=r"(d[2]), "=r"(d[3]) : "r"(s));
}
__device__ __forceinline__ void ldsm4t(unsigned int* d, const void* p)
{
    unsigned int s = (unsigned int)__cvta_generic_to_shared(p);
    asm volatile("ldmatrix.sync.aligned.m8n8.x4.trans.shared.b16 {%0,%1,%2,%3}, [%4];"
                 : "=r"(d[0]), "=r"(d[1]), "=r"(d[2]), "=r"(d[3]) : "r"(s));
}
__device__ __forceinline__ void mma16816(float* c, const unsigned int* a,
                                         unsigned int b0, unsigned int b1)
{
    asm volatile("mma.sync.aligned.m16n8k16.row.col.f32.bf16.bf16.f32 "
                 "{%0,%1,%2,%3}, {%4,%5,%6,%7}, {%8,%9}, {%0,%1,%2,%3};"
                 : "+f"(c[0]), "+f"(c[1]), "+f"(c[2]), "+f"(c[3])
                 : "r"(a[0]), "r"(a[1]), "r"(a[2]), "r"(a[3]), "r"(b0), "r"(b1));
}

__global__ __launch_bounds__(256, 2) void gemm_bf16(
    const __nv_bfloat16* __restrict__ A, const __nv_bfloat16* __restrict__ B,
    const float* __restrict__ bias, float* __restrict__ C,
    int M, int N, int Kc, int relu)
{
    __shared__ __nv_bfloat16 As[2][128][40];
    __shared__ __nv_bfloat16 Bs[2][32][136];

    const int tid = threadIdx.x;
    const int lane = tid & 31;
    const int warp = tid >> 5;
    const int wm = warp >> 2;
    const int wn = warp & 3;
    const int row0 = blockIdx.y * 128;
    const int col0 = blockIdx.x * 128;

    const int ar = tid >> 1;
    const int ac = (tid & 1) << 4;
    const int arow = row0 + ar;
    const bool apred = arow < M;
    const __nv_bfloat16* Abase = A + (size_t)(apred ? arow : 0) * Kc + ac;

    const int br = tid >> 3;
    const int bc = (tid & 7) << 4;
    const int bcol = col0 + bc;
    const bool bp0 = bcol < N;
    const bool bp1 = (bcol + 8) < N;
    const int bc0 = bp0 ? bcol : 0;
    const int bc1 = bp1 ? (bcol + 8) : 0;

    float acc[4][4][4];
#pragma unroll
    for (int i = 0; i < 4; i++) {
#pragma unroll
        for (int j = 0; j < 4; j++) {
#pragma unroll
            for (int q = 0; q < 4; q++) acc[i][j][q] = 0.f;
        }
    }

    const int iters = Kc >> 5;

    cpa16(&As[0][ar][ac], Abase, apred);
    cpa16(&As[0][ar][ac + 8], Abase + 8, apred);
    {
        const __nv_bfloat16* Bb = B + (size_t)br * N;
        cpa16(&Bs[0][br][bc], Bb + bc0, bp0);
        cpa16(&Bs[0][br][bc + 8], Bb + bc1, bp1);
    }
    asm volatile("cp.async.commit_group;" ::: "memory");

    int s = 0;
    for (int it = 0; it < iters; it++) {
        if (it + 1 < iters) {
            const int kk = (it + 1) << 5;
            cpa16(&As[s ^ 1][ar][ac], Abase + kk, apred);
            cpa16(&As[s ^ 1][ar][ac + 8], Abase + kk + 8, apred);
            const __nv_bfloat16* Bb = B + (size_t)(kk + br) * N;
            cpa16(&Bs[s ^ 1][br][bc], Bb + bc0, bp0);
            cpa16(&Bs[s ^ 1][br][bc + 8], Bb + bc1, bp1);
            asm volatile("cp.async.commit_group;" ::: "memory");
            asm volatile("cp.async.wait_group 1;" ::: "memory");
        } else {
            asm volatile("cp.async.wait_group 0;" ::: "memory");
        }
        __syncthreads();

#pragma unroll
        for (int k16 = 0; k16 < 2; k16++) {
            unsigned int af[4][4];
#pragma unroll
            for (int mi = 0; mi < 4; mi++) {
                ldsm4(af[mi], &As[s][wm * 64 + mi * 16 + (lane & 15)]
                                    [k16 * 16 + ((lane >> 4) << 3)]);
            }
            unsigned int bfr[2][4];
#pragma unroll
            for (int g = 0; g < 2; g++) {
                ldsm4t(bfr[g], &Bs[s][k16 * 16 + (lane & 15)]
                                     [wn * 32 + g * 16 + ((lane >> 4) << 3)]);
            }
#pragma unroll
            for (int mi = 0; mi < 4; mi++) {
#pragma unroll
                for (int ni = 0; ni < 4; ni++) {
                    mma16816(acc[mi][ni], af[mi],
                             bfr[ni >> 1][(ni & 1) * 2],
                             bfr[ni >> 1][(ni & 1) * 2 + 1]);
                }
            }
        }
        __syncthreads();
        s ^= 1;
    }

#pragma unroll
    for (int mi = 0; mi < 4; mi++) {
        int r = row0 + wm * 64 + mi * 16 + (lane >> 2);
#pragma unroll
        for (int ni = 0; ni < 4; ni++) {
            int c = col0 + wn * 32 + ni * 8 + ((lane & 3) << 1);
            if (c < N) {
                float b0 = bias[c];
                float b1 = bias[c + 1];
                if (r < M) {
                    float o0 = acc[mi][ni][0] + b0;
                    float o1 = acc[mi][ni][1] + b1;
                    if (relu) { o0 = fmaxf(o0, 0.f); o1 = fmaxf(o1, 0.f); }
                    *(float2*)(C + (size_t)r * N + c) = make_float2(o0, o1);
                }
                if (r + 8 < M) {
                    float o2 = acc[mi][ni][2] + b0;
                    float o3 = acc[mi][ni][3] + b1;
                    if (relu) { o2 = fmaxf(o2, 0.f); o3 = fmaxf(o3, 0.f); }
                    *(float2*)(C + (size_t)(r + 8) * N + c) = make_float2(o2, o3);
                }
            }
        }
    }
}

// ================= CSR construction ========================================
__global__ void zero_cnt(int* cnt)
{
    int i = blockIdx.x * blockDim.x + threadIdx.x;
    if (i < N_NODES) cnt[i] = 0;
}
__global__ void hist_rows(const int* __restrict__ row, int* cnt)
{
    int i = blockIdx.x * blockDim.x + threadIdx.x;
    if (i < E_EDGES) atomicAdd(&cnt[row[i]], 1);
}
__global__ void exscan(const int* __restrict__ cnt, int* rowptr)
{
    __shared__ int part[256];
    int t = threadIdx.x;
    int base = t * 40;
    int s = 0;
#pragma unroll
    for (int j = 0; j < 40; j++) {
        int idx = base + j;
        if (idx < N_NODES) s += cnt[idx];
    }
    part[t] = s;
    __syncthreads();
    for (int off = 1; off < 256; off <<= 1) {
        int v = (t >= off) ? part[t - off] : 0;
        __syncthreads();
        part[t] += v;
        __syncthreads();
    }
    int run = (t > 0) ? part[t - 1] : 0;
#pragma unroll
    for (int j = 0; j < 40; j++) {
        int idx = base + j;
        if (idx < N_NODES) { rowptr[idx] = run; run += cnt[idx]; }
    }
    if (t == 255) rowptr[N_NODES] = part[255];
}
__global__ void copy_cur(const int* __restrict__ rowptr, int* cur)
{
    int i = blockIdx.x * blockDim.x + threadIdx.x;
    if (i < N_NODES) cur[i] = rowptr[i];
}
__global__ void scatter_csr(const int* __restrict__ row, const int* __restrict__ col,
                            const float* __restrict__ val, int* cur,
                            int* __restrict__ oc, float* __restrict__ ov)
{
    int i = blockIdx.x * blockDim.x + threadIdx.x;
    if (i < E_EDGES) {
        int r = row[i];
        int p = atomicAdd(&cur[r], 1);
        oc[p] = col[i];
        ov[p] = val[i];
    }
}

// ================= fW softmax ==============================================
__global__ void fw_softmax(const float* __restrict__ fw_rna,
                           const float* __restrict__ fw_atac, float* out)
{
    int t = threadIdx.x;
    if (t >= 4) return;
    const float* src = (t < 2) ? (fw_rna + t * (K_HOPS + 1))
                               : (fw_atac + (t - 2) * (K_HOPS + 1));
    float m = -1e30f;
    for (int k = 0; k <= K_HOPS; k++) m = fmaxf(m, src[k]);
    float e[K_HOPS + 1];
    float s = 0.f;
    for (int k = 0; k <= K_HOPS; k++) { e[k] = expf(src[k] - m); s += e[k]; }
    float inv = 1.f / s;
    for (int k = 0; k <= K_HOPS; k++) out[t * (K_HOPS + 1) + k] = e[k] * inv;
}

// ================= propagation =============================================
__global__ void init_acc(const float* __restrict__ h, float* __restrict__ acc,
                         const float* __restrict__ wp)
{
    int i = blockIdx.x * blockDim.x + threadIdx.x;
    if (i >= N_NODES * HID / 4) return;
    float w = wp[0];
    int r = i >> 6;
    int c4 = i & 63;
    float4 v = ((const float4*)h)[i];
    float4 o = make_float4(w * v.x, w * v.y, w * v.z, w * v.w);
    ((float4*)(acc + (long long)r * 512))[c4] = o;
}

__global__ __launch_bounds__(256) void spmm_fused(
    const int* __restrict__ rowptr, const int* __restrict__ cols,
    const float* __restrict__ vals, const float* __restrict__ x,
    float* __restrict__ xout, float* __restrict__ acc,
    const float* __restrict__ wp)
{
    int r = blockIdx.x * 8 + (threadIdx.x >> 5);
    if (r >= N_NODES) return;
    int lane = threadIdx.x & 31;
    float w = wp[0];
    int e0 = rowptr[r];
    int e1 = rowptr[r + 1];

    float4 s0 = make_float4(0.f, 0.f, 0.f, 0.f);
    float4 s1 = make_float4(0.f, 0.f, 0.f, 0.f);
    for (int e = e0; e < e1; e++) {
        int c = cols[e];
        float v = vals[e];
        const float4* xp = (const float4*)(x + (long long)c * HID);
        float4 a = xp[lane];
        float4 b = xp[lane + 32];
        s0.x += v * a.x; s0.y += v * a.y; s0.z += v * a.z; s0.w += v * a.w;
        s1.x += v * b.x; s1.y += v * b.y; s1.z += v * b.z; s1.w += v * b.w;
    }
    float4* xo = (float4*)(xout + (long long)r * HID);
    xo[lane] = s0;
    xo[lane + 32] = s1;
    float4* ap = (float4*)(acc + (long long)r * 512);
    float4 c0 = ap[lane];
    c0.x += w * s0.x; c0.y += w * s0.y; c0.z += w * s0.z; c0.w += w * s0.w;
    ap[lane] = c0;
    float4 c1 = ap[lane + 32];
    c1.x += w * s1.x; c1.y += w * s1.y; c1.z += w * s1.z; c1.w += w * s1.w;
    ap[lane + 32] = c1;
}

// ================= attention fusion ========================================
__global__ __launch_bounds__(256) void att_fuse(
    const float* __restrict__ zr, const float* __restrict__ za,
    const float* __restrict__ Wa, const float* __restrict__ ba,
    float* __restrict__ z, float* __restrict__ wout)
{
    int r = blockIdx.x * 8 + (threadIdx.x >> 5);
    if (r >= N_NODES) return;
    int lane = threadIdx.x & 31;
    const float* zrr = zr + (long long)r * HID;
    const float* zar = za + (long long)r * HID;

    float p0 = 0.f;
    float p1 = 0.f;
    for (int c = lane; c < HID; c += 32) {
        float v = zrr[c];
        p0 += v * Wa[c * 2];
        p1 += v * Wa[c * 2 + 1];
        float u = zar[c];
        p0 += u * Wa[(HID + c) * 2];
        p1 += u * Wa[(HID + c) * 2 + 1];
    }
#pragma unroll
    for (int off = 16; off; off >>= 1) {
        p0 += __shfl_xor_sync(0xffffffffu, p0, off);
        p1 += __shfl_xor_sync(0xffffffffu, p1, off);
    }
    float l0 = p0 + ba[0];
    float l1 = p1 + ba[1];
    float m = fmaxf(l0, l1);
    float e0 = expf(l0 - m);
    float e1 = expf(l1 - m);
    float inv = 1.f / (e0 + e1);
    float w0 = e0 * inv;
    float w1 = e1 * inv;
    if (lane == 0) {
        wout[r * 2 + 0] = w0;
        wout[r * 2 + 1] = w1;
    }
    for (int c = lane; c < HID; c += 32)
        z[(long long)r * HID + c] = w0 * zrr[c] + w1 * zar[c];
}

// ================= host orchestration ======================================
static inline int cgrid(long long total, int tpb)
{
    long long b = (total + tpb - 1) / tpb;
    if (b > 65535) b = 65535;
    return (int)b;
}

extern "C" void kernel_launch(void* const* d_in, const int* in_sizes, int n_in,
                              void* d_out, int out_size)
{
    const float* X_rna  = (const float*)d_in[0];
    const float* X_atac = (const float*)d_in[1];
    const int*   row1 = (const int*)d_in[2];
    const int*   col1 = (const int*)d_in[3];
    const float* val1 = (const float*)d_in[4];
    const int*   row2 = (const int*)d_in[5];
    const int*   col2 = (const int*)d_in[6];
    const float* val2 = (const float*)d_in[7];
    const float* Wi_rna  = (const float*)d_in[8];
    const float* bi_rna  = (const float*)d_in[9];
    const float* fW_rna  = (const float*)d_in[10];
    const float* Wo_rna  = (const float*)d_in[11];
    const float* bo_rna  = (const float*)d_in[12];
    const float* Wi_atac = (const float*)d_in[13];
    const float* bi_atac = (const float*)d_in[14];
    const float* fW_atac = (const float*)d_in[15];
    const float* Wo_atac = (const float*)d_in[16];
    const float* bo_atac = (const float*)d_in[17];
    const float* Wa = (const float*)d_in[18];
    const float* ba = (const float*)d_in[19];
    const float* Wd1_rna  = (const float*)d_in[20];
    const float* bd1_rna  = (const float*)d_in[21];
    const float* Wd2_rna  = (const float*)d_in[22];
    const float* bd2_rna  = (const float*)d_in[23];
    const float* Wd1_atac = (const float*)d_in[24];
    const float* bd1_atac = (const float*)d_in[25];
    const float* Wd2_atac = (const float*)d_in[26];
    const float* bd2_atac = (const float*)d_in[27];

    float* out = (float*)d_out;
    float* out_z     = out;
    float* out_zrna  = out + (size_t)N_NODES * HID;
    float* out_zatac = out + 2 * (size_t)N_NODES * HID;
    float* out_w     = out + 3 * (size_t)N_NODES * HID;
    float* out_rrec  = out_w + (size_t)N_NODES * 2;
    float* out_arec  = out_rrec + (size_t)N_NODES * D_RNA;

    float *pb0 = 0, *pb1 = 0, *pb2 = 0, *pb3 = 0, *pb4 = 0;
    float *pzr = 0, *pza = 0, *pfw = 0, *pvals = 0;
    int *prp = 0, *pcols = 0, *pcnt = 0, *pcur = 0;
    __nv_bfloat16 *pac = 0, *pawor = 0, *pawoa = 0, *paz = 0, *padr = 0, *pada = 0;
    __nv_bfloat16 *pwir0 = 0, *pwir1 = 0, *pwia0 = 0, *pwia1 = 0;
    __nv_bfloat16 *pwor = 0, *pwoa = 0, *pd1r = 0, *pd1a = 0, *pd2r = 0, *pd2a = 0;
    cudaGetSymbolAddress((void**)&pb0, g_b0);
    cudaGetSymbolAddress((void**)&pb1, g_b1);
    cudaGetSymbolAddress((void**)&pb2, g_b2);
    cudaGetSymbolAddress((void**)&pb3, g_b3);
    cudaGetSymbolAddress((void**)&pb4, g_b4);
    cudaGetSymbolAddress((void**)&pzr, g_zcr);
    cudaGetSymbolAddress((void**)&pza, g_zca);
    cudaGetSymbolAddress((void**)&pfw, g_fw);
    cudaGetSymbolAddress((void**)&prp, g_rowptr);
    cudaGetSymbolAddress((void**)&pcols, g_cols);
    cudaGetSymbolAddress((void**)&pvals, g_vals);
    cudaGetSymbolAddress((void**)&pcnt, g_cnt);
    cudaGetSymbolAddress((void**)&pcur, g_cur);
    cudaGetSymbolAddress((void**)&pac, g_acat);
    cudaGetSymbolAddress((void**)&pawor, g_awor);
    cudaGetSymbolAddress((void**)&pawoa, g_awoa);
    cudaGetSymbolAddress((void**)&paz, g_az);
    cudaGetSymbolAddress((void**)&padr, g_adr);
    cudaGetSymbolAddress((void**)&pada, g_ada);
    cudaGetSymbolAddress((void**)&pwir0, g_bwir0);
    cudaGetSymbolAddress((void**)&pwir1, g_bwir1);
    cudaGetSymbolAddress((void**)&pwia0, g_bwia0);
    cudaGetSymbolAddress((void**)&pwia1, g_bwia1);
    cudaGetSymbolAddress((void**)&pwor, g_bwor);
    cudaGetSymbolAddress((void**)&pwoa, g_bwoa);
    cudaGetSymbolAddress((void**)&pd1r, g_bd1r);
    cudaGetSymbolAddress((void**)&pd1a, g_bd1a);
    cudaGetSymbolAddress((void**)&pd2r, g_bd2r);
    cudaGetSymbolAddress((void**)&pd2a, g_bd2a);

    // ---- fork/join second stream (graph-capture-safe event pattern) ----
    bool ok = true;
    cudaEvent_t eFork, eB1, eG0, eCsr, eG1, eRna, eG2, eG3, eWoR, eAtt, eDone;
    cudaEvent_t* evs[11] = {&eFork, &eB1, &eG0, &eCsr, &eG1, &eRna,
                            &eG2, &eG3, &eWoR, &eAtt, &eDone};
    for (int i = 0; i < 11; i++) {
        if (ok && cudaEventCreateWithFlags(evs[i], cudaEventDisableTiming) != cudaSuccess)
            ok = false;
    }
    cudaStream_t s2 = 0;
    if (ok) {
        if (cudaStreamCreateWithFlags(&s2, cudaStreamNonBlocking) != cudaSuccess)
            s2 = 0;
    }
#define REC0(e) do { if (ok) cudaEventRecord(e, 0); } while (0)
#define REC2(e) do { if (ok) cudaEventRecord(e, s2); } while (0)
#define W0(e)   do { if (ok) cudaStreamWaitEvent(0, e, 0); } while (0)
#define W2(e)   do { if (ok) cudaStreamWaitEvent(s2, e, 0); } while (0)

    const dim3 gH(2, 79);
    const int TPB = 256;

    // ---------------- s0 head / s2 CSR ----------------
    REC0(eFork);
    W2(eFork);
    // s2: CSR build for both orders
    for (int o = 0; o < 2; o++) {
        const int* rw = o ? row2 : row1;
        const int* cl = o ? col2 : col1;
        const float* vl = o ? val2 : val1;
        zero_cnt<<<40, 256, 0, s2>>>(pcnt + o * N_NODES);
        hist_rows<<<1250, 256, 0, s2>>>(rw, pcnt + o * N_NODES);
        exscan<<<1, 256, 0, s2>>>(pcnt + o * N_NODES, prp + o * (N_NODES + 1));
        copy_cur<<<40, 256, 0, s2>>>(prp + o * (N_NODES + 1), pcur + o * N_NODES);
        scatter_csr<<<1250, 256, 0, s2>>>(rw, cl, vl, pcur + o * N_NODES,
                                          pcols + o * E_EDGES, pvals + o * E_EDGES);
    }
    REC2(eCsr);

    // s0: fw softmax + rna conversions + G_rna0
    fw_softmax<<<1, 32>>>(fW_rna, fW_atac, pfw);
    conv_a<<<cgrid((long long)N_NODES * D_RNA / 2, TPB), TPB>>>(X_rna, pac, N_NODES, D_RNA, 6016);
    pad_a<<<cgrid((long long)N_NODES * 16, TPB), TPB>>>(pac, N_NODES, 6016, 6000);
    conv_b<<<cgrid((long long)D_RNA * HID / 2, TPB), TPB>>>(Wi_rna, pwir0, D_RNA, HID);
    pad_b<<<cgrid(16LL * HID, TPB), TPB>>>(pwir0 + (size_t)6000 * HID, 16 * HID);
    conv_b<<<cgrid((long long)D_RNA * HID / 2, TPB), TPB>>>(Wi_rna + (size_t)D_RNA * HID,
                                                            pwir1, D_RNA, HID);
    pad_b<<<cgrid(16LL * HID, TPB), TPB>>>(pwir1 + (size_t)6000 * HID, 16 * HID);
    REC0(eB1);
    gemm_bf16<<<gH, 256>>>(pac, pwir0, bi_rna, pb0, N_NODES, HID, 6016, 0);
    REC0(eG0);

    // s2: G_rna1, then atac conversions + atac Wi GEMMs, all off critical path
    W2(eB1);
    gemm_bf16<<<gH, 256, 0, s2>>>(pac, pwir1, bi_rna + HID, pb2, N_NODES, HID, 6016, 0);
    REC2(eG1);
    W2(eG0);  // g_acat free only after G_rna0 (s0) and G_rna1 (s2 program order)
    conv_a<<<cgrid((long long)N_NODES * D_ATAC / 2, TPB), TPB, 0, s2>>>(
        X_atac, pac, N_NODES, D_ATAC, 15008);
    pad_a<<<cgrid((long long)N_NODES * 8, TPB), TPB, 0, s2>>>(pac, N_NODES, 15008, 15000);
    conv_b<<<cgrid((long long)D_ATAC * HID / 2, TPB), TPB, 0, s2>>>(Wi_atac, pwia0, D_ATAC, HID);
    pad_b<<<cgrid(8LL * HID, TPB), TPB, 0, s2>>>(pwia0 + (size_t)15000 * HID, 8 * HID);
    gemm_bf16<<<gH, 256, 0, s2>>>(pac, pwia0, bi_atac, pb3, N_NODES, HID, 15008, 0);
    REC2(eG2);
    conv_b<<<cgrid((long long)D_ATAC * HID / 2, TPB), TPB, 0, s2>>>(
        Wi_atac + (size_t)D_ATAC * HID, pwia1, D_ATAC, HID);
    pad_b<<<cgrid(8LL * HID, TPB), TPB, 0, s2>>>(pwia1 + (size_t)15000 * HID, 8 * HID);
    gemm_bf16<<<gH, 256, 0, s2>>>(pac, pwia1, bi_atac + HID, pb4, N_NODES, HID, 15008, 0);
    REC2(eG3);

    // ---------------- s0: the four propagation chains ----------------
    W0(eCsr);
    // chain R0: rna order 0, h=b0, ping {b0,b1}, acc zcat_r[:,0:256]
    {
        const float* wrow = pfw + 0 * (K_HOPS + 1);
        init_acc<<<2500, 256>>>(pb0, pzr, wrow);
        float* bufs[2] = {pb0, pb1};
        for (int k = 1; k <= K_HOPS; k++)
            spmm_fused<<<1250, 256>>>(prp, pcols, pvals,
                                      bufs[(k + 1) & 1], bufs[k & 1], pzr, wrow + k);
    }
    // chain R1: rna order 1, h=b2, ping {b2,b0}
    W0(eG1);
    {
        const float* wrow = pfw + 1 * (K_HOPS + 1);
        init_acc<<<2500, 256>>>(pb2, pzr + HID, wrow);
        float* bufs[2] = {pb2, pb0};
        for (int k = 1; k <= K_HOPS; k++)
            spmm_fused<<<1250, 256>>>(prp + (N_NODES + 1), pcols + E_EDGES,
                                      pvals + E_EDGES,
                                      bufs[(k + 1) & 1], bufs[k & 1], pzr + HID, wrow + k);
    }
    REC0(eRna);
    // chain A0: atac order 0, h=b3, ping {b3,b1}
    W0(eG2);
    {
        const float* wrow = pfw + 2 * (K_HOPS + 1);
        init_acc<<<2500, 256>>>(pb3, pza, wrow);
        float* bufs[2] = {pb3, pb1};
        for (int k = 1; k <= K_HOPS; k++)
            spmm_fused<<<1250, 256>>>(prp, pcols, pvals,
                                      bufs[(k + 1) & 1], bufs[k & 1], pza, wrow + k);
    }
    // chain A1: atac order 1, h=b4, ping {b4,b2}
    W0(eG3);
    {
        const float* wrow = pfw + 3 * (K_HOPS + 1);
        init_acc<<<2500, 256>>>(pb4, pza + HID, wrow);
        float* bufs[2] = {pb4, pb2};
        for (int k = 1; k <= K_HOPS; k++)
            spmm_fused<<<1250, 256>>>(prp + (N_NODES + 1), pcols + E_EDGES,
                                      pvals + E_EDGES,
                                      bufs[(k + 1) & 1], bufs[k & 1], pza + HID, wrow + k);
    }

    // s2: Wo_rna overlapped with A chains
    W2(eRna);
    conv_a<<<cgrid((long long)N_NODES * 512 / 2, TPB), TPB, 0, s2>>>(pzr, pawor, N_NODES, 512, 1536);
    conv_b<<<cgrid(512LL * HID / 2, TPB), TPB, 0, s2>>>(Wo_rna, pwor, 512, HID);
    gemm_bf16<<<gH, 256, 0, s2>>>(pawor, pwor, bo_rna, out_zrna, N_NODES, HID, 1536, 0);
    REC2(eWoR);

    // s0 tail: Wo_atac, attention, shared z conversion
    conv_a<<<cgrid((long long)N_NODES * 512 / 2, TPB), TPB>>>(pza, pawoa, N_NODES, 512, 1536);
    conv_b<<<cgrid(512LL * HID / 2, TPB), TPB>>>(Wo_atac, pwoa, 512, HID);
    gemm_bf16<<<gH, 256>>>(pawoa, pwoa, bo_atac, out_zatac, N_NODES, HID, 1536, 0);
    W0(eWoR);
    att_fuse<<<1250, 256>>>(out_zrna, out_zatac, Wa, ba, out_z, out_w);
    conv_a<<<cgrid((long long)N_NODES * HID / 2, TPB), TPB>>>(out_z, paz, N_NODES, HID, 768);
    REC0(eAtt);

    // s2: rna decoder
    W2(eAtt);
    conv_b<<<cgrid((long long)HID * HID / 2, TPB), TPB, 0, s2>>>(Wd1_rna, pd1r, HID, HID);
    gemm_bf16<<<gH, 256, 0, s2>>>(paz, pd1r, bd1_rna, pb2, N_NODES, HID, 768, 1);
    conv_a<<<cgrid((long long)N_NODES * HID / 2, TPB), TPB, 0, s2>>>(pb2, padr, N_NODES, HID, 768);
    conv_b<<<cgrid((long long)HID * D_RNA / 2, TPB), TPB, 0, s2>>>(Wd2_rna, pd2r, HID, D_RNA);
    gemm_bf16<<<dim3(16, 79), 256, 0, s2>>>(padr, pd2r, bd2_rna, out_rrec,
                                            N_NODES, D_RNA, 768, 0);
    REC2(eDone);

    // s0: atac decoder
    conv_b<<<cgrid((long long)HID * HID / 2, TPB), TPB>>>(Wd1_atac, pd1a, HID, HID);
    gemm_bf16<<<gH, 256>>>(paz, pd1a, bd1_atac, pb3, N_NODES, HID, 768, 1);
    conv_a<<<cgrid((long long)N_NODES * HID / 2, TPB), TPB>>>(pb3, pada, N_NODES, HID, 768);
    conv_b<<<cgrid((long long)HID * D_ATAC / 2, TPB), TPB>>>(Wd2_atac, pd2a, HID, D_ATAC);
    gemm_bf16<<<dim3(40, 79), 256>>>(pada, pd2a, bd2_atac, out_arec,
                                     N_NODES, D_ATAC, 768, 0);

    // join s2 back into s0 before returning
    W0(eDone);
#undef REC0
#undef REC2
#undef W0
#undef W2
}